// round 6
// baseline (speedup 1.0000x reference)
#include <cuda_runtime.h>
#include <cuda_fp16.h>
#include <cstdint>
#include <cstddef>

// ---------------- problem constants ----------------
#define BATCH 16384
#define JNT   17
#define FIN   256
#define FOUT  256
#define MROWS (BATCH * JNT)          // 278528 = 2176 * 128
#define KTOT  (3 * FIN)              // 768

// GEMM tiling (fp16: BK=64 = 32 pairs per iter)
#define BM 128
#define BN 256
#define NKIT 12                      // t -> (part = t%3, fc = t/3)
#define ASTRIDE 40                   // uint32 per A smem row (32 pair-slots + 8 pad)
#define BSTRIDE 40
#define ASZW (BM * ASTRIDE)          // 5120 uint32 per Az buffer
#define BSZW (BN * BSTRIDE)          // 10240 uint32 per B buffer

// smem layout (uint32 offsets)
#define SADJ_OFF 0                   // 289 floats
#define AZ_OFF   320
#define B_OFF    (AZ_OFF + 2 * ASZW)         // 10560
#define SMEM_WORDS (B_OFF + 2 * BSZW)        // 31040
#define SMEM_BYTES (SMEM_WORDS * 4)          // 124160

#define NTHREADS 384                 // 8 consumer warps + 4 producer warps

// ---------------- device scratch ----------------
__device__ uint32_t g_wb[(size_t)NKIT * BN * 32];    // Wcat prepacked fp16 pairs

// ---------------- helpers ----------------
__device__ __forceinline__ uint32_t smem_u32(const void* p) {
    uint32_t a;
    asm("{ .reg .u64 t; cvta.to.shared.u64 t, %1; cvt.u32.u64 %0, t; }" : "=r"(a) : "l"(p));
    return a;
}
__device__ __forceinline__ void cp16(uint32_t dst, const void* src) {
    asm volatile("cp.async.cg.shared.global [%0], [%1], 16;" :: "r"(dst), "l"(src));
}
#define CP_COMMIT() asm volatile("cp.async.commit_group;" ::: "memory")
#define CP_WAIT0()  asm volatile("cp.async.wait_group 0;" ::: "memory")

#define NBAR_SYNC(id)   asm volatile("bar.sync %0, %1;"   :: "r"(id), "r"(NTHREADS) : "memory")
#define NBAR_ARRIVE(id) asm volatile("bar.arrive %0, %1;" :: "r"(id), "r"(NTHREADS) : "memory")
// barrier ids: full[buf] = 1+buf, empty[buf] = 3+buf

__device__ __forceinline__ void mma_f16(float* d, uint32_t a0, uint32_t a1,
                                        uint32_t a2, uint32_t a3,
                                        uint32_t b0, uint32_t b1) {
    asm volatile(
        "mma.sync.aligned.m16n8k16.row.col.f32.f16.f16.f32 "
        "{%0,%1,%2,%3}, {%4,%5,%6,%7}, {%8,%9}, {%0,%1,%2,%3};"
        : "+f"(d[0]), "+f"(d[1]), "+f"(d[2]), "+f"(d[3])
        : "r"(a0), "r"(a1), "r"(a2), "r"(a3), "r"(b0), "r"(b1));
}
__device__ __forceinline__ uint32_t pack2(float lo, float hi) {
    __half2 h = __floats2half2_rn(lo, hi);
    return *reinterpret_cast<uint32_t*>(&h);
}

// pair-interleave: pair q -> slot (q&3)*2 + (q>>2) within each 8-group,
// so slots (2c, 2c+1) hold pairs (c, c+4) -> one LDS.64 per mma fragment half.

// ---------------- kernel 0: prepack Wcat fp16 pairs per stage ----------------
__global__ void __launch_bounds__(256) wprep_kernel(const float* __restrict__ W) {
    int idx = blockIdx.x * 256 + threadIdx.x;       // 12*256*32 = 98304
    int s = idx & 31;
    int n = (idx >> 5) & 255;
    int t = idx >> 13;
    int part = t % 3, fc = t / 3;
    int sp = s & 7;
    int q = (sp >> 1) + ((sp & 1) << 2);            // inverse interleave
    int P = fc * 32 + (s >> 3) * 8 + q;             // pair index within part
    int k0 = part * 256 + 2 * P;
    g_wb[idx] = pack2(W[k0 * FOUT + n], W[(k0 + 1) * FOUT + n]);
}

// ---------------- producer z compute ----------------
template <int PART>
__device__ __forceinline__ void z_units(const float* __restrict__ sadj,
                                        const float2* __restrict__ xb,   // x pairs + fc*32
                                        uint32_t* __restrict__ Az,
                                        int ptid, int wbase, int b0) {
    #pragma unroll
    for (int rep = 0; rep < 3; rep++) {
        int u = ptid + rep * 128;                   // 288 units: 9 batches x 32 pairs
        if (u < 288) {
            int bl = u >> 5, f2l = u & 31;
            int bg = b0 + bl; if (bg > BATCH - 1) bg = BATCH - 1;
            const float2* xp = xb + (size_t)bg * JNT * 128 + f2l;
            float2 xr[JNT];
            #pragma unroll
            for (int j = 0; j < JNT; j++) xr[j] = xp[(size_t)j * 128];
            const int slot = (f2l >> 3) * 8 + ((f2l & 3) << 1) + ((f2l >> 2) & 1);
            const int lr0 = wbase + bl * JNT;
            #pragma unroll
            for (int i = 0; i < JNT; i++) {
                float vx = 0.f, vy = 0.f;
                if (PART == 0) {
                    float a = sadj[i * JNT + i];
                    vx = a * xr[i].x; vy = a * xr[i].y;
                }
                if (PART == 1) {
                    #pragma unroll
                    for (int j = i + 1; j < JNT; j++) {
                        float a = sadj[i * JNT + j];
                        vx += a * xr[j].x; vy += a * xr[j].y;
                    }
                }
                if (PART == 2) {
                    #pragma unroll
                    for (int j = 0; j < i; j++) {
                        float a = sadj[i * JNT + j];
                        vx += a * xr[j].x; vy += a * xr[j].y;
                    }
                }
                int lr = lr0 + i;
                if (lr >= 0 && lr < BM) Az[lr * ASTRIDE + slot] = pack2(vx, vy);
            }
        }
    }
}

// ---------------- fused kernel ----------------
__global__ void __launch_bounds__(NTHREADS, 1)
fused_kernel(const float* __restrict__ x, const float* __restrict__ adj,
             const float* __restrict__ bias, float* __restrict__ out) {
    extern __shared__ uint32_t sm[];
    float* smf = (float*)sm;
    const uint32_t sb = smem_u32(sm);
    const int tid = threadIdx.x;

    const int mbase = blockIdx.x * BM;
    const int b0 = mbase / JNT;
    const int wbase = b0 * JNT - mbase;             // in (-17, 0]

    for (int i = tid; i < JNT * JNT; i += NTHREADS) smf[SADJ_OFF + i] = adj[i];
    __syncthreads();

    if (tid < 256) {
        // ---------------- consumers: 8 warps, 128x256 tile ----------------
        const int wid = tid >> 5, lane = tid & 31;
        const int warp_m = wid & 1, warp_n = wid >> 1;
        const int r = lane >> 2, c = lane & 3;

        float acc[128];
        #pragma unroll
        for (int i = 0; i < 128; i++) acc[i] = 0.0f;

        for (int t = 0; t < NKIT; t++) {
            const int buf = t & 1;
            NBAR_SYNC(1 + buf);                      // Az[buf], B[buf] ready
            const uint32_t* As = sm + AZ_OFF + buf * ASZW;
            const uint32_t* Bs = sm + B_OFF + buf * BSZW;
            #pragma unroll
            for (int s = 0; s < 4; s++) {            // 4 k16-steps
                uint2 aF[4][2];
                #pragma unroll
                for (int mt = 0; mt < 4; mt++) {
                    const uint32_t* ap = As + (warp_m * 64 + mt * 16 + r) * ASTRIDE + s * 8 + 2 * c;
                    aF[mt][0] = *(const uint2*)ap;
                    aF[mt][1] = *(const uint2*)(ap + 8 * ASTRIDE);
                }
                uint2 bF[8];
                #pragma unroll
                for (int nt = 0; nt < 8; nt++) {
                    const uint32_t* bp = Bs + (warp_n * 64 + nt * 8 + r) * BSTRIDE + s * 8 + 2 * c;
                    bF[nt] = *(const uint2*)bp;
                }
                #pragma unroll
                for (int mt = 0; mt < 4; mt++)
                    #pragma unroll
                    for (int nt = 0; nt < 8; nt++)
                        mma_f16(&acc[(mt * 8 + nt) * 4],
                                aF[mt][0].x, aF[mt][1].x, aF[mt][0].y, aF[mt][1].y,
                                bF[nt].x, bF[nt].y);
            }
            NBAR_ARRIVE(3 + buf);                    // Az[buf]/B[buf] free
        }

        // epilogue: + bias -> out
        #pragma unroll
        for (int mt = 0; mt < 4; mt++) {
            size_t gm = (size_t)mbase + warp_m * 64 + mt * 16 + r;
            float* o0 = out + gm * FOUT;
            #pragma unroll
            for (int nt = 0; nt < 8; nt++) {
                int col = warp_n * 64 + nt * 8 + 2 * c;
                float b0v = __ldg(bias + col), b1v = __ldg(bias + col + 1);
                const float* a = &acc[(mt * 8 + nt) * 4];
                *(float2*)(o0 + col)            = make_float2(a[0] + b0v, a[1] + b1v);
                *(float2*)(o0 + 8 * FOUT + col) = make_float2(a[2] + b0v, a[3] + b1v);
            }
        }
    } else {
        // ---------------- producers: 4 warps ----------------
        const int ptid = tid - 256;                  // 0..127
        for (int t = 0; t < NKIT; t++) {
            const int buf = t & 1;
            if (t >= 2) NBAR_SYNC(3 + buf);          // wait buffer consumed

            // B stage t -> smem (cp.async)
            const uint32_t* wb = g_wb + (size_t)t * (BN * 32);
            uint32_t bd = sb + (B_OFF + buf * BSZW) * 4;
            #pragma unroll
            for (int qq = 0; qq < 16; qq++) {
                int id = ptid + qq * 128;            // 2048 chunks
                int row = id >> 3, ck = id & 7;
                cp16(bd + (row * BSTRIDE + ck * 4) * 4, wb + id * 4);
            }
            CP_COMMIT();

            // z stage (aggregation) for iter t
            const int part = t % 3, fc = t / 3;
            uint32_t* Az = sm + AZ_OFF + buf * ASZW;
            const float2* xb = (const float2*)x + fc * 32;
            if (part == 0)      z_units<0>(smf + SADJ_OFF, xb, Az, ptid, wbase, b0);
            else if (part == 1) z_units<1>(smf + SADJ_OFF, xb, Az, ptid, wbase, b0);
            else                z_units<2>(smf + SADJ_OFF, xb, Az, ptid, wbase, b0);

            CP_WAIT0();                              // B arrived
            NBAR_SYNC(1 + buf);                      // publish full[buf]
        }
    }
}

// ---------------- launch ----------------
extern "C" void kernel_launch(void* const* d_in, const int* in_sizes, int n_in,
                              void* d_out, int out_size) {
    const float* x    = (const float*)d_in[0];   // [16384,17,256]
    const float* W    = (const float*)d_in[1];   // [3,256,256]
    const float* adj  = (const float*)d_in[2];   // [17,17]
    const float* bias = (const float*)d_in[3];   // [256]
    float* out = (float*)d_out;                  // [16384,17,256]

    cudaFuncSetAttribute(fused_kernel, cudaFuncAttributeMaxDynamicSharedMemorySize, SMEM_BYTES);

    wprep_kernel<<<(NKIT * BN * 32) / 256, 256>>>(W);
    fused_kernel<<<MROWS / BM, NTHREADS, SMEM_BYTES>>>(x, adj, bias, out);
}

// round 7
// speedup vs baseline: 1.3028x; 1.3028x over previous
#include <cuda_runtime.h>
#include <cuda_fp16.h>
#include <cstdint>
#include <cstddef>

// ---------------- problem constants ----------------
#define BATCH 16384
#define JNT   17
#define FIN   256
#define FOUT  256
#define MROWS (BATCH * JNT)          // 278528 = 2176 * 128
#define KTOT  (3 * FIN)              // 768
#define PROW  384                    // uint32 (fp16-pairs) per z row

// GEMM tiling: CTA 128x128, BK=64 (32 pairs), 2-stage, 2 CTAs/SM
#define BM 128
#define BN 128
#define NKIT 12
#define ASTRIDE 40                   // uint32 per A smem row (32 pair-slots + 8 pad)
#define BSTRIDE 40
#define ASZW (BM * ASTRIDE)          // 5120 uint32
#define BSZW (BN * BSTRIDE)          // 5120 uint32
#define STGW (ASZW + BSZW)           // 10240 uint32 per stage
#define NSTAGE 2
#define SMEM_BYTES (NSTAGE * STGW * 4)   // 81920 bytes -> 2 CTAs/SM

// ---------------- device scratch ----------------
__device__ uint32_t g_z[(size_t)MROWS * PROW];       // z fp16 pairs, interleaved (~428MB)
__device__ uint32_t g_wb[(size_t)NKIT * 256 * 32];   // Wcat prepacked fp16 (~393KB)

// ---------------- helpers ----------------
__device__ __forceinline__ uint32_t smem_u32(const void* p) {
    uint32_t a;
    asm("{ .reg .u64 t; cvta.to.shared.u64 t, %1; cvt.u32.u64 %0, t; }" : "=r"(a) : "l"(p));
    return a;
}
__device__ __forceinline__ void cp16(uint32_t dst, const void* src) {
    asm volatile("cp.async.cg.shared.global [%0], [%1], 16;" :: "r"(dst), "l"(src));
}
#define CP_COMMIT() asm volatile("cp.async.commit_group;" ::: "memory")
#define CP_WAIT1()  asm volatile("cp.async.wait_group 1;" ::: "memory")
#define CP_WAIT0()  asm volatile("cp.async.wait_group 0;" ::: "memory")

__device__ __forceinline__ void mma_f16(float* d, uint32_t a0, uint32_t a1,
                                        uint32_t a2, uint32_t a3,
                                        uint32_t b0, uint32_t b1) {
    asm volatile(
        "mma.sync.aligned.m16n8k16.row.col.f32.f16.f16.f32 "
        "{%0,%1,%2,%3}, {%4,%5,%6,%7}, {%8,%9}, {%0,%1,%2,%3};"
        : "+f"(d[0]), "+f"(d[1]), "+f"(d[2]), "+f"(d[3])
        : "r"(a0), "r"(a1), "r"(a2), "r"(a3), "r"(b0), "r"(b1));
}
__device__ __forceinline__ uint32_t pack2(float lo, float hi) {
    __half2 h = __floats2half2_rn(lo, hi);
    return *reinterpret_cast<uint32_t*>(&h);
}

// pair-interleave: pair q -> slot (q&3)*2 + (q>>2) within each 8-group,
// so slots (2c, 2c+1) hold pairs (c, c+4) -> one LDS.64 per mma fragment half.

// ---------------- kernel 1: aggregation -> z  (+ merged W prepack) ----------------
// block handles 2 batches; thread (sub = tid>>7, p = tid&127) -> features 2p, 2p+1.
// Blocks 0..383 additionally prepack Wcat into g_wb (98304 elements).
__global__ void __launch_bounds__(256) agg_kernel(const float* __restrict__ x,
                                                  const float* __restrict__ adj,
                                                  const float* __restrict__ W) {
    __shared__ float sx[2 * JNT * FIN];
    __shared__ float sadj[JNT * JNT];
    const int tid = threadIdx.x;
    const int b0 = blockIdx.x * 2;

    // merged wprep: g_wb[t][n][slot], slot s holds k-pairs (2P, 2P+1),
    // P = t*32 + (s>>3)*8 + invperm(s&7); k = global row of Wcat [768,256].
    if (blockIdx.x < 384) {
        int idx = blockIdx.x * 256 + tid;
        int s = idx & 31;
        int n = (idx >> 5) & 255;
        int t = idx >> 13;
        int sp = s & 7;
        int q = (sp >> 1) + ((sp & 1) << 2);
        int P = t * 32 + (s >> 3) * 8 + q;
        int k0 = 2 * P;
        g_wb[idx] = pack2(W[k0 * FOUT + n], W[(k0 + 1) * FOUT + n]);
    }

    const float4* xs = (const float4*)(x + (size_t)b0 * JNT * FIN);
    float4* sd = (float4*)sx;
    for (int t = tid; t < 2 * JNT * FIN / 4; t += 256) sd[t] = xs[t];
    for (int t = tid; t < JNT * JNT; t += 256) sadj[t] = adj[t];
    __syncthreads();

    const int sub = tid >> 7;
    const int p = tid & 127;
    const float* xb = sx + sub * JNT * FIN;

    float xa[JNT], xc[JNT];
    #pragma unroll
    for (int j = 0; j < JNT; j++) {
        float2 v = ((const float2*)(xb + j * FIN))[p];
        xa[j] = v.x; xc[j] = v.y;
    }

    const int q = p & 7;
    const int sl = (p >> 3) * 8 + ((q & 3) * 2 + (q >> 2));
    uint32_t* zr = g_z + (size_t)(b0 + sub) * JNT * PROW;

    #pragma unroll
    for (int i = 0; i < JNT; i++) {
        float d0 = sadj[i * JNT + i] * xa[i];
        float d1 = sadj[i * JNT + i] * xc[i];
        float s1a = 0.f, s1c = 0.f, s2a = 0.f, s2c = 0.f;
        #pragma unroll
        for (int j = 0; j < JNT; j++) {
            float a = sadj[i * JNT + j];
            if (j > i) { s1a += a * xa[j]; s1c += a * xc[j]; }
            if (j < i) { s2a += a * xa[j]; s2c += a * xc[j]; }
        }
        uint32_t* zi = zr + i * PROW;
        zi[sl]       = pack2(d0, d1);
        zi[128 + sl] = pack2(s1a, s1c);
        zi[256 + sl] = pack2(s2a, s2c);
    }
}

// ---------------- kernel 2: GEMM  out = z @ Wcat + bias ----------------
// CTA 128x128, 8 warps of 64x32 (warp_m in {0,1}, warp_n in {0..3}),
// 2-stage cp.async, targets 2 CTAs/SM.
__device__ __forceinline__ void load_stage(uint32_t sb, int t, int s, int tid,
                                           size_t mbase, int nbase) {
    // A: z rows [mbase..mbase+127], slots [t*32, t*32+32)
    const uint32_t* za = g_z + mbase * PROW + t * 32;
    uint32_t as = sb + (uint32_t)s * STGW * 4;
    #pragma unroll
    for (int qq = 0; qq < 4; qq++) {
        int id = tid + qq * 256;                 // 1024 chunks
        int row = id >> 3, ck = id & 7;
        cp16(as + (row * ASTRIDE + ck * 4) * 4, za + (size_t)row * PROW + ck * 4);
    }
    // B: prepacked half [t][nbase..nbase+127][32], contiguous 16KB
    const uint32_t* wb = g_wb + ((size_t)t * 256 + nbase) * 32;
    uint32_t bs = sb + ((uint32_t)s * STGW + ASZW) * 4;
    #pragma unroll
    for (int qq = 0; qq < 4; qq++) {
        int id = tid + qq * 256;                 // 1024 chunks
        int row = id >> 3, ck = id & 7;
        cp16(bs + (row * BSTRIDE + ck * 4) * 4, wb + id * 4);
    }
}

__global__ void __launch_bounds__(256, 2) gemm_kernel(float* __restrict__ out,
                                                      const float* __restrict__ bias) {
    extern __shared__ uint32_t sm[];
    const uint32_t sb = smem_u32(sm);
    const int tid = threadIdx.x;
    const int wid = tid >> 5;
    const int lane = tid & 31;
    const int warp_m = wid & 1;      // 2 x 64 = 128 M
    const int warp_n = wid >> 1;     // 4 x 32 = 128 N
    const int r = lane >> 2;
    const int c = lane & 3;
    const size_t mbase = (size_t)blockIdx.x * BM;
    const int nbase = blockIdx.y * BN;

    float acc[64];
    #pragma unroll
    for (int i = 0; i < 64; i++) acc[i] = 0.0f;

    load_stage(sb, 0, 0, tid, mbase, nbase); CP_COMMIT();

    for (int t = 0; t < NKIT; t++) {
        __syncthreads();                         // all done reading stage t-1's buffer
        if (t + 1 < NKIT) {
            load_stage(sb, t + 1, (t + 1) & 1, tid, mbase, nbase);
            CP_COMMIT();
            CP_WAIT1();                          // stage t arrived (t+1 may be pending)
        } else {
            CP_WAIT0();
        }
        __syncthreads();                         // stage t visible to all

        const uint32_t* As = sm + (t & 1) * STGW;
        const uint32_t* Bs = As + ASZW;

        #pragma unroll
        for (int s = 0; s < 4; s++) {            // 4 k16-steps
            uint2 aF[4][2];
            #pragma unroll
            for (int mt = 0; mt < 4; mt++) {
                const uint32_t* ap = As + (warp_m * 64 + mt * 16 + r) * ASTRIDE + s * 8 + 2 * c;
                aF[mt][0] = *(const uint2*)ap;                  // pairs c, c+4 of row r
                aF[mt][1] = *(const uint2*)(ap + 8 * ASTRIDE);  // row r+8
            }
            uint2 bF[4];
            #pragma unroll
            for (int nt = 0; nt < 4; nt++) {
                const uint32_t* bp = Bs + (warp_n * 32 + nt * 8 + r) * BSTRIDE + s * 8 + 2 * c;
                bF[nt] = *(const uint2*)bp;
            }
            #pragma unroll
            for (int mt = 0; mt < 4; mt++)
                #pragma unroll
                for (int nt = 0; nt < 4; nt++)
                    mma_f16(&acc[(mt * 4 + nt) * 4],
                            aF[mt][0].x, aF[mt][1].x, aF[mt][0].y, aF[mt][1].y,
                            bF[nt].x, bF[nt].y);
        }
    }

    // epilogue: + bias, write fp32 out
    #pragma unroll
    for (int mt = 0; mt < 4; mt++) {
        size_t gm = mbase + warp_m * 64 + mt * 16 + r;
        float* o0 = out + gm * FOUT;
        #pragma unroll
        for (int nt = 0; nt < 4; nt++) {
            int col = nbase + warp_n * 32 + nt * 8 + 2 * c;
            float b0 = __ldg(bias + col), b1 = __ldg(bias + col + 1);
            const float* a = &acc[(mt * 4 + nt) * 4];
            *(float2*)(o0 + col)            = make_float2(a[0] + b0, a[1] + b1);
            *(float2*)(o0 + 8 * FOUT + col) = make_float2(a[2] + b0, a[3] + b1);
        }
    }
}

// ---------------- launch ----------------
extern "C" void kernel_launch(void* const* d_in, const int* in_sizes, int n_in,
                              void* d_out, int out_size) {
    const float* x    = (const float*)d_in[0];   // [16384,17,256]
    const float* W    = (const float*)d_in[1];   // [3,256,256] == Wcat[768,256]
    const float* adj  = (const float*)d_in[2];   // [17,17]
    const float* bias = (const float*)d_in[3];   // [256]
    float* out = (float*)d_out;                  // [16384,17,256]

    cudaFuncSetAttribute(gemm_kernel, cudaFuncAttributeMaxDynamicSharedMemorySize, SMEM_BYTES);

    agg_kernel<<<BATCH / 2, 256>>>(x, adj, W);
    dim3 grid(MROWS / BM, 2);
    gemm_kernel<<<grid, 256, SMEM_BYTES>>>(out, bias);
}

// round 8
// speedup vs baseline: 1.5162x; 1.1638x over previous
#include <cuda_runtime.h>
#include <cuda_fp16.h>
#include <cstdint>
#include <cstddef>

// ---------------- problem constants ----------------
#define BATCH 16384
#define JNT   17
#define FIN   256
#define FOUT  256
#define MROWS (BATCH * JNT)          // 278528 = 2176 * 128
#define PROW  384                    // uint32 (fp16-pairs) per z row

// GEMM tiling: CTA 128x128, BK=64 (32 pairs), 2-stage, 2 CTAs/SM
#define BM 128
#define BN 128
#define NKIT 12
#define ASTRIDE 40
#define BSTRIDE 40
#define ASZW (BM * ASTRIDE)          // 5120 uint32
#define BSZW (BN * BSTRIDE)          // 5120 uint32
#define STGW (ASZW + BSZW)           // 10240 uint32 per stage
#define SMEM_BYTES (2 * STGW * 4)    // 81920 -> 2 CTAs/SM

// agg smem: 4 batches of x + adj
#define AGG_SMEM ((4 * JNT * FIN + JNT * JNT) * 4)   // 70788 bytes

// ---------------- device scratch ----------------
__device__ uint32_t g_z[(size_t)MROWS * PROW];       // z fp16 pairs (~428MB)
__device__ uint32_t g_wb[(size_t)NKIT * 256 * 32];   // Wcat prepacked fp16

// ---------------- helpers ----------------
__device__ __forceinline__ uint32_t smem_u32(const void* p) {
    uint32_t a;
    asm("{ .reg .u64 t; cvta.to.shared.u64 t, %1; cvt.u32.u64 %0, t; }" : "=r"(a) : "l"(p));
    return a;
}
__device__ __forceinline__ void cp16(uint32_t dst, const void* src) {
    asm volatile("cp.async.cg.shared.global [%0], [%1], 16;" :: "r"(dst), "l"(src));
}
#define CP_COMMIT() asm volatile("cp.async.commit_group;" ::: "memory")
#define CP_WAIT1()  asm volatile("cp.async.wait_group 1;" ::: "memory")
#define CP_WAIT0()  asm volatile("cp.async.wait_group 0;" ::: "memory")

__device__ __forceinline__ void mma_f16(float* d, uint32_t a0, uint32_t a1,
                                        uint32_t a2, uint32_t a3,
                                        uint32_t b0, uint32_t b1) {
    asm volatile(
        "mma.sync.aligned.m16n8k16.row.col.f32.f16.f16.f32 "
        "{%0,%1,%2,%3}, {%4,%5,%6,%7}, {%8,%9}, {%0,%1,%2,%3};"
        : "+f"(d[0]), "+f"(d[1]), "+f"(d[2]), "+f"(d[3])
        : "r"(a0), "r"(a1), "r"(a2), "r"(a3), "r"(b0), "r"(b1));
}
__device__ __forceinline__ uint32_t pack2(float lo, float hi) {
    __half2 h = __floats2half2_rn(lo, hi);
    return *reinterpret_cast<uint32_t*>(&h);
}

// pair-interleave: within each 8-pair group, slot (2m, 2m+1) holds pairs (m, m+4);
// thread owning features (16G+2m, +1, +8, +9) writes one aligned uint2.

// ---------------- kernel 1: aggregation -> z  (+ merged W prepack) ----------------
// block = 256 threads, 4 batches; thread: sub = tid>>6, u = tid&63, G = u>>2, m = u&3.
__global__ void __launch_bounds__(256) agg_kernel(const float* __restrict__ x,
                                                  const float* __restrict__ adj,
                                                  const float* __restrict__ W) {
    extern __shared__ float sdyn[];
    float* sx   = sdyn;                       // 4*17*256
    float* sadj = sdyn + 4 * JNT * FIN;       // 289
    const int tid = threadIdx.x;
    const int b0 = blockIdx.x * 4;

    // merged wprep: 98304 elements over first 384 blocks
    if (blockIdx.x < 384) {
        int idx = blockIdx.x * 256 + tid;
        int s = idx & 31;
        int n = (idx >> 5) & 255;
        int t = idx >> 13;
        int sp = s & 7;
        int q = (sp >> 1) + ((sp & 1) << 2);
        int P = t * 32 + (s >> 3) * 8 + q;
        int k0 = 2 * P;
        g_wb[idx] = pack2(W[k0 * FOUT + n], W[(k0 + 1) * FOUT + n]);
    }

    const float4* xs = (const float4*)(x + (size_t)b0 * JNT * FIN);
    float4* sd = (float4*)sx;
    #pragma unroll
    for (int t = tid; t < 4 * JNT * FIN / 4; t += 256) sd[t] = xs[t];
    for (int t = tid; t < JNT * JNT; t += 256) sadj[t] = adj[t];
    __syncthreads();

    const int sub = tid >> 6;                 // batch within block
    const int u = tid & 63;
    const int G = u >> 2, m = u & 3;
    const int f0 = G * 16 + m * 2;
    const float* xb = sx + sub * JNT * FIN;

    float2 xlo[JNT], xhi[JNT];                // features (f0, f0+1), (f0+8, f0+9)
    #pragma unroll
    for (int j = 0; j < JNT; j++) {
        xlo[j] = *(const float2*)(xb + j * FIN + f0);
        xhi[j] = *(const float2*)(xb + j * FIN + f0 + 8);
    }

    const int slot = G * 8 + 2 * m;           // even -> 8B-aligned uint2
    uint32_t* zr = g_z + (size_t)(b0 + sub) * JNT * PROW;

    #pragma unroll
    for (int i = 0; i < JNT; i++) {
        float ad = sadj[i * JNT + i];
        float2 d_lo = make_float2(ad * xlo[i].x, ad * xlo[i].y);
        float2 d_hi = make_float2(ad * xhi[i].x, ad * xhi[i].y);
        float2 s1l = make_float2(0.f, 0.f), s1h = make_float2(0.f, 0.f);
        float2 s2l = make_float2(0.f, 0.f), s2h = make_float2(0.f, 0.f);
        #pragma unroll
        for (int j = 0; j < JNT; j++) {
            float a = sadj[i * JNT + j];
            if (j > i) {
                s1l.x += a * xlo[j].x; s1l.y += a * xlo[j].y;
                s1h.x += a * xhi[j].x; s1h.y += a * xhi[j].y;
            }
            if (j < i) {
                s2l.x += a * xlo[j].x; s2l.y += a * xlo[j].y;
                s2h.x += a * xhi[j].x; s2h.y += a * xhi[j].y;
            }
        }
        uint32_t* zi = zr + i * PROW;
        *(uint2*)(zi + slot)       = make_uint2(pack2(d_lo.x, d_lo.y), pack2(d_hi.x, d_hi.y));
        *(uint2*)(zi + 128 + slot) = make_uint2(pack2(s1l.x, s1l.y), pack2(s1h.x, s1h.y));
        *(uint2*)(zi + 256 + slot) = make_uint2(pack2(s2l.x, s2l.y), pack2(s2h.x, s2h.y));
    }
}

// ---------------- kernel 2: GEMM  out = z @ Wcat + bias ----------------
__device__ __forceinline__ void load_stage(uint32_t sb, int t, int s, int tid,
                                           size_t mbase, int nbase) {
    const uint32_t* za = g_z + mbase * PROW + t * 32;
    uint32_t as = sb + (uint32_t)s * STGW * 4;
    #pragma unroll
    for (int qq = 0; qq < 4; qq++) {
        int id = tid + qq * 256;
        int row = id >> 3, ck = id & 7;
        cp16(as + (row * ASTRIDE + ck * 4) * 4, za + (size_t)row * PROW + ck * 4);
    }
    const uint32_t* wb = g_wb + ((size_t)t * 256 + nbase) * 32;
    uint32_t bs = sb + ((uint32_t)s * STGW + ASZW) * 4;
    #pragma unroll
    for (int qq = 0; qq < 4; qq++) {
        int id = tid + qq * 256;
        int row = id >> 3, ck = id & 7;
        cp16(bs + (row * BSTRIDE + ck * 4) * 4, wb + id * 4);
    }
}

__global__ void __launch_bounds__(256, 2) gemm_kernel(float* __restrict__ out,
                                                      const float* __restrict__ bias) {
    extern __shared__ uint32_t sm[];
    const uint32_t sb = smem_u32(sm);
    const int tid = threadIdx.x;
    const int wid = tid >> 5;
    const int lane = tid & 31;
    const int warp_m = wid & 1;
    const int warp_n = wid >> 1;
    const int r = lane >> 2;
    const int c = lane & 3;
    // N-half on blockIdx.x: the 2 CTAs sharing an M-tile are adjacent bids -> A hits L2
    const int nbase = blockIdx.x * BN;
    const size_t mbase = (size_t)blockIdx.y * BM;

    float acc[64];
    #pragma unroll
    for (int i = 0; i < 64; i++) acc[i] = 0.0f;

    load_stage(sb, 0, 0, tid, mbase, nbase); CP_COMMIT();

    for (int t = 0; t < NKIT; t++) {
        __syncthreads();                     // everyone done reading buffer (t+1)&1
        if (t + 1 < NKIT) {
            load_stage(sb, t + 1, (t + 1) & 1, tid, mbase, nbase);
            CP_COMMIT();
            CP_WAIT1();
        } else {
            CP_WAIT0();
        }
        __syncthreads();                     // stage t visible

        const uint32_t* As = sm + (t & 1) * STGW;
        const uint32_t* Bs = As + ASZW;

        #pragma unroll
        for (int s = 0; s < 4; s++) {
            uint2 aF[4][2];
            #pragma unroll
            for (int mt = 0; mt < 4; mt++) {
                const uint32_t* ap = As + (warp_m * 64 + mt * 16 + r) * ASTRIDE + s * 8 + 2 * c;
                aF[mt][0] = *(const uint2*)ap;
                aF[mt][1] = *(const uint2*)(ap + 8 * ASTRIDE);
            }
            uint2 bF[4];
            #pragma unroll
            for (int nt = 0; nt < 4; nt++) {
                const uint32_t* bp = Bs + (warp_n * 32 + nt * 8 + r) * BSTRIDE + s * 8 + 2 * c;
                bF[nt] = *(const uint2*)bp;
            }
            #pragma unroll
            for (int mt = 0; mt < 4; mt++)
                #pragma unroll
                for (int nt = 0; nt < 4; nt++)
                    mma_f16(&acc[(mt * 4 + nt) * 4],
                            aF[mt][0].x, aF[mt][1].x, aF[mt][0].y, aF[mt][1].y,
                            bF[nt].x, bF[nt].y);
        }
    }

    #pragma unroll
    for (int mt = 0; mt < 4; mt++) {
        size_t gm = mbase + warp_m * 64 + mt * 16 + r;
        float* o0 = out + gm * FOUT;
        #pragma unroll
        for (int nt = 0; nt < 4; nt++) {
            int col = nbase + warp_n * 32 + nt * 8 + 2 * c;
            float b0 = __ldg(bias + col), b1 = __ldg(bias + col + 1);
            const float* a = &acc[(mt * 4 + nt) * 4];
            *(float2*)(o0 + col)            = make_float2(a[0] + b0, a[1] + b1);
            *(float2*)(o0 + 8 * FOUT + col) = make_float2(a[2] + b0, a[3] + b1);
        }
    }
}

// ---------------- launch ----------------
extern "C" void kernel_launch(void* const* d_in, const int* in_sizes, int n_in,
                              void* d_out, int out_size) {
    const float* x    = (const float*)d_in[0];   // [16384,17,256]
    const float* W    = (const float*)d_in[1];   // [3,256,256]
    const float* adj  = (const float*)d_in[2];   // [17,17]
    const float* bias = (const float*)d_in[3];   // [256]
    float* out = (float*)d_out;                  // [16384,17,256]

    cudaFuncSetAttribute(agg_kernel, cudaFuncAttributeMaxDynamicSharedMemorySize, AGG_SMEM);
    cudaFuncSetAttribute(gemm_kernel, cudaFuncAttributeMaxDynamicSharedMemorySize, SMEM_BYTES);

    agg_kernel<<<BATCH / 4, 256, AGG_SMEM>>>(x, adj, W);
    dim3 grid(2, MROWS / BM);
    gemm_kernel<<<grid, 256, SMEM_BYTES>>>(out, bias);
}

// round 9
// speedup vs baseline: 1.5395x; 1.0154x over previous
#include <cuda_runtime.h>
#include <cuda_fp16.h>
#include <cstdint>
#include <cstddef>

// ---------------- problem constants ----------------
#define BATCH 16384
#define JNT   17
#define FIN   256
#define FOUT  256
#define MROWS (BATCH * JNT)          // 278528 = 2176 * 128
#define PROW  384                    // uint32 (fp16-pairs) per z row

// GEMM tiling: CTA 128x128, BK=64 (32 pairs); A 3-stage, B 2-stage; 2 CTAs/SM
#define BM 128
#define BN 128
#define NKIT 12
#define ASTRIDE 40
#define BSTRIDE 40
#define ASZW (BM * ASTRIDE)          // 5120 uint32 per A stage
#define BSZW (BN * BSTRIDE)          // 5120 uint32 per B stage
#define B_OFF (3 * ASZW)
#define SMEM_WORDS (3 * ASZW + 2 * BSZW)     // 25600
#define SMEM_BYTES (SMEM_WORDS * 4)          // 102400 -> 2 CTAs/SM

// agg smem: 4 batches of x + adj
#define AGG_SMEM ((4 * JNT * FIN + JNT * JNT) * 4)   // 70788 bytes

// ---------------- device scratch ----------------
__device__ uint32_t g_z[(size_t)MROWS * PROW];       // z fp16 pairs (~428MB)
__device__ uint32_t g_wb[(size_t)NKIT * 256 * 32];   // Wcat prepacked fp16

// ---------------- helpers ----------------
__device__ __forceinline__ uint32_t smem_u32(const void* p) {
    uint32_t a;
    asm("{ .reg .u64 t; cvta.to.shared.u64 t, %1; cvt.u32.u64 %0, t; }" : "=r"(a) : "l"(p));
    return a;
}
__device__ __forceinline__ void cp16(uint32_t dst, const void* src) {
    asm volatile("cp.async.cg.shared.global [%0], [%1], 16;" :: "r"(dst), "l"(src));
}
#define CP_COMMIT() asm volatile("cp.async.commit_group;" ::: "memory")
#define CP_WAIT3()  asm volatile("cp.async.wait_group 3;" ::: "memory")

__device__ __forceinline__ void mma_f16(float* d, uint32_t a0, uint32_t a1,
                                        uint32_t a2, uint32_t a3,
                                        uint32_t b0, uint32_t b1) {
    asm volatile(
        "mma.sync.aligned.m16n8k16.row.col.f32.f16.f16.f32 "
        "{%0,%1,%2,%3}, {%4,%5,%6,%7}, {%8,%9}, {%0,%1,%2,%3};"
        : "+f"(d[0]), "+f"(d[1]), "+f"(d[2]), "+f"(d[3])
        : "r"(a0), "r"(a1), "r"(a2), "r"(a3), "r"(b0), "r"(b1));
}
__device__ __forceinline__ uint32_t pack2(float lo, float hi) {
    __half2 h = __floats2half2_rn(lo, hi);
    return *reinterpret_cast<uint32_t*>(&h);
}

// pair-interleave: within each 8-pair group, slot (2m, 2m+1) holds pairs (m, m+4).

// ---------------- kernel 1: aggregation -> z  (+ merged W prepack) ----------------
__global__ void __launch_bounds__(256) agg_kernel(const float* __restrict__ x,
                                                  const float* __restrict__ adj,
                                                  const float* __restrict__ W) {
    extern __shared__ float sdyn[];
    float* sx   = sdyn;                       // 4*17*256
    float* sadj = sdyn + 4 * JNT * FIN;       // 289
    const int tid = threadIdx.x;
    const int b0 = blockIdx.x * 4;

    if (blockIdx.x < 384) {                   // merged W prepack
        int idx = blockIdx.x * 256 + tid;
        int s = idx & 31;
        int n = (idx >> 5) & 255;
        int t = idx >> 13;
        int sp = s & 7;
        int q = (sp >> 1) + ((sp & 1) << 2);
        int P = t * 32 + (s >> 3) * 8 + q;
        int k0 = 2 * P;
        g_wb[idx] = pack2(W[k0 * FOUT + n], W[(k0 + 1) * FOUT + n]);
    }

    const float4* xs = (const float4*)(x + (size_t)b0 * JNT * FIN);
    float4* sd = (float4*)sx;
    #pragma unroll
    for (int t = tid; t < 4 * JNT * FIN / 4; t += 256) sd[t] = xs[t];
    for (int t = tid; t < JNT * JNT; t += 256) sadj[t] = adj[t];
    __syncthreads();

    const int sub = tid >> 6;
    const int u = tid & 63;
    const int G = u >> 2, m = u & 3;
    const int f0 = G * 16 + m * 2;
    const float* xb = sx + sub * JNT * FIN;

    float2 xlo[JNT], xhi[JNT];
    #pragma unroll
    for (int j = 0; j < JNT; j++) {
        xlo[j] = *(const float2*)(xb + j * FIN + f0);
        xhi[j] = *(const float2*)(xb + j * FIN + f0 + 8);
    }

    const int slot = G * 8 + 2 * m;
    uint32_t* zr = g_z + (size_t)(b0 + sub) * JNT * PROW;

    #pragma unroll
    for (int i = 0; i < JNT; i++) {
        float ad = sadj[i * JNT + i];
        float2 d_lo = make_float2(ad * xlo[i].x, ad * xlo[i].y);
        float2 d_hi = make_float2(ad * xhi[i].x, ad * xhi[i].y);
        float2 s1l = make_float2(0.f, 0.f), s1h = make_float2(0.f, 0.f);
        float2 s2l = make_float2(0.f, 0.f), s2h = make_float2(0.f, 0.f);
        #pragma unroll
        for (int j = 0; j < JNT; j++) {
            float a = sadj[i * JNT + j];
            if (j > i) {
                s1l.x += a * xlo[j].x; s1l.y += a * xlo[j].y;
                s1h.x += a * xhi[j].x; s1h.y += a * xhi[j].y;
            }
            if (j < i) {
                s2l.x += a * xlo[j].x; s2l.y += a * xlo[j].y;
                s2h.x += a * xhi[j].x; s2h.y += a * xhi[j].y;
            }
        }
        uint32_t* zi = zr + i * PROW;
        *(uint2*)(zi + slot)       = make_uint2(pack2(d_lo.x, d_lo.y), pack2(d_hi.x, d_hi.y));
        *(uint2*)(zi + 128 + slot) = make_uint2(pack2(s1l.x, s1l.y), pack2(s1h.x, s1h.y));
        *(uint2*)(zi + 256 + slot) = make_uint2(pack2(s2l.x, s2l.y), pack2(s2h.x, s2h.y));
    }
}

// ---------------- kernel 2: GEMM  out = z @ Wcat + bias ----------------
__device__ __forceinline__ void load_a(uint32_t sb, int t, int s, int tid, size_t mbase) {
    const uint32_t* za = g_z + mbase * PROW + t * 32;
    uint32_t as = sb + (uint32_t)s * ASZW * 4;
    #pragma unroll
    for (int qq = 0; qq < 4; qq++) {
        int id = tid + qq * 256;
        int row = id >> 3, ck = id & 7;
        cp16(as + (row * ASTRIDE + ck * 4) * 4, za + (size_t)row * PROW + ck * 4);
    }
}
__device__ __forceinline__ void load_b(uint32_t sb, int t, int s, int tid, int nbase) {
    const uint32_t* wb = g_wb + ((size_t)t * 256 + nbase) * 32;
    uint32_t bs = sb + ((uint32_t)(B_OFF + s * BSZW)) * 4;
    #pragma unroll
    for (int qq = 0; qq < 4; qq++) {
        int id = tid + qq * 256;
        int row = id >> 3, ck = id & 7;
        cp16(bs + (row * BSTRIDE + ck * 4) * 4, wb + id * 4);
    }
}

__global__ void __launch_bounds__(256, 2) gemm_kernel(float* __restrict__ out,
                                                      const float* __restrict__ bias) {
    extern __shared__ uint32_t sm[];
    const uint32_t sb = smem_u32(sm);
    const int tid = threadIdx.x;
    const int wid = tid >> 5;
    const int lane = tid & 31;
    const int warp_m = wid & 1;
    const int warp_n = wid >> 1;
    const int r = lane >> 2;
    const int c = lane & 3;
    // N-half on blockIdx.x: the 2 CTAs sharing an M-tile are adjacent bids -> A hits L2
    const int nbase = blockIdx.x * BN;
    const size_t mbase = (size_t)blockIdx.y * BM;

    float acc[64];
    #pragma unroll
    for (int i = 0; i < 64; i++) acc[i] = 0.0f;

    // prologue: group {A0,B0}, group {A1}
    load_a(sb, 0, 0, tid, mbase);
    load_b(sb, 0, 0, tid, nbase);
    CP_COMMIT();
    load_a(sb, 1, 1, tid, mbase);
    CP_COMMIT();

    int abuf = 0;                             // t % 3
    for (int t = 0; t < NKIT; t++) {
        __syncthreads();                      // all reads of iter t-1 buffers done

        // commit order per iter: {B t+1}, {A t+2}. wait_group 3 -> A(t), B(t) landed.
        if (t + 1 < NKIT) load_b(sb, t + 1, (t + 1) & 1, tid, nbase);
        CP_COMMIT();
        if (t + 2 < NKIT) {
            int nb = abuf + 2; if (nb >= 3) nb -= 3;
            load_a(sb, t + 2, nb, tid, mbase);
        }
        CP_COMMIT();
        CP_WAIT3();
        __syncthreads();                      // stage t visible

        const uint32_t* As = sm + abuf * ASZW;
        const uint32_t* Bs = sm + B_OFF + (t & 1) * BSZW;

        #pragma unroll
        for (int s = 0; s < 4; s++) {
            uint2 aF[4][2];
            #pragma unroll
            for (int mt = 0; mt < 4; mt++) {
                const uint32_t* ap = As + (warp_m * 64 + mt * 16 + r) * ASTRIDE + s * 8 + 2 * c;
                aF[mt][0] = *(const uint2*)ap;
                aF[mt][1] = *(const uint2*)(ap + 8 * ASTRIDE);
            }
            uint2 bF[4];
            #pragma unroll
            for (int nt = 0; nt < 4; nt++) {
                const uint32_t* bp = Bs + (warp_n * 32 + nt * 8 + r) * BSTRIDE + s * 8 + 2 * c;
                bF[nt] = *(const uint2*)bp;
            }
            #pragma unroll
            for (int mt = 0; mt < 4; mt++)
                #pragma unroll
                for (int nt = 0; nt < 4; nt++)
                    mma_f16(&acc[(mt * 4 + nt) * 4],
                            aF[mt][0].x, aF[mt][1].x, aF[mt][0].y, aF[mt][1].y,
                            bF[nt].x, bF[nt].y);
        }

        abuf = abuf + 1; if (abuf == 3) abuf = 0;
    }

    #pragma unroll
    for (int mt = 0; mt < 4; mt++) {
        size_t gm = mbase + warp_m * 64 + mt * 16 + r;
        float* o0 = out + gm * FOUT;
        #pragma unroll
        for (int nt = 0; nt < 4; nt++) {
            int col = nbase + warp_n * 32 + nt * 8 + 2 * c;
            float b0 = __ldg(bias + col), b1 = __ldg(bias + col + 1);
            const float* a = &acc[(mt * 4 + nt) * 4];
            *(float2*)(o0 + col)            = make_float2(a[0] + b0, a[1] + b1);
            *(float2*)(o0 + 8 * FOUT + col) = make_float2(a[2] + b0, a[3] + b1);
        }
    }
}

// ---------------- launch ----------------
extern "C" void kernel_launch(void* const* d_in, const int* in_sizes, int n_in,
                              void* d_out, int out_size) {
    const float* x    = (const float*)d_in[0];   // [16384,17,256]
    const float* W    = (const float*)d_in[1];   // [3,256,256]
    const float* adj  = (const float*)d_in[2];   // [17,17]
    const float* bias = (const float*)d_in[3];   // [256]
    float* out = (float*)d_out;                  // [16384,17,256]

    cudaFuncSetAttribute(agg_kernel, cudaFuncAttributeMaxDynamicSharedMemorySize, AGG_SMEM);
    cudaFuncSetAttribute(gemm_kernel, cudaFuncAttributeMaxDynamicSharedMemorySize, SMEM_BYTES);

    agg_kernel<<<BATCH / 4, 256, AGG_SMEM>>>(x, adj, W);
    dim3 grid(2, MROWS / BM);
    gemm_kernel<<<grid, 256, SMEM_BYTES>>>(out, bias);
}